// round 11
// baseline (speedup 1.0000x reference)
#include <cuda_runtime.h>
#include <cuda_fp16.h>
#include <math.h>
#include <stdint.h>

#define BB 2
#define HH 480
#define WW 640
#define DD 256
#define HC 60
#define WC 80
#define NN 4800          // HC*WC
#define TOTAL_PIX (BB*HH*WW)

// ---------------- device scratch ----------------
// acc: 0 pos1, 1 neg1, 2 npos1, 3 pos2, 4 neg2, 5 npos2, 6 normalization, 7 desc_sum
__device__ double g_acc[8];   // static zero-init; finalize re-zeros after each use
__device__ __align__(16) __half g_dnorm[BB*NN*DD];   // (b, ij, d) fp16 normalized
__device__ __align__(16) __half g_wdnorm[BB*NN*DD];
__device__ float4 g_rowgeo[BB*NN];   // {wy, wx, vm_c, 0}
__device__ float4 g_colgeo[BB*NN];   // {cy, cx, wvm_c, 0}

// ---------------- helpers ----------------
__device__ __forceinline__ float warpsum(float v) {
    #pragma unroll
    for (int o = 16; o; o >>= 1) v += __shfl_down_sync(0xffffffffu, v, o);
    return v;
}

__device__ __forceinline__ uint32_t smem_u32(const void* p) {
    uint32_t a;
    asm("{ .reg .u64 t; cvta.to.shared.u64 t, %1; cvt.u32.u64 %0, t; }" : "=r"(a) : "l"(p));
    return a;
}

__device__ __forceinline__ void cp_async16(uint32_t dst, const void* src, uint32_t bytes) {
    asm volatile("cp.async.cg.shared.global [%0], [%1], 16, %2;"
                 :: "r"(dst), "l"(src), "r"(bytes) : "memory");
}
#define CP_COMMIT() asm volatile("cp.async.commit_group;" ::: "memory")
#define CP_WAIT(n)  asm volatile("cp.async.wait_group %0;" :: "n"(n) : "memory")

// ---------------- detector losses + normalization sum (float4) ----------------
__global__ void detector_kernel(const float4* __restrict__ prob,
                                const float4* __restrict__ ht,
                                const float4* __restrict__ vm,
                                const float4* __restrict__ wprob,
                                const float4* __restrict__ wht,
                                const float4* __restrict__ wvm) {
    float vals[7] = {0, 0, 0, 0, 0, 0, 0};
    const int n4 = TOTAL_PIX / 4;
    for (int i = blockIdx.x * blockDim.x + threadIdx.x; i < n4;
         i += gridDim.x * blockDim.x) {
        float4 p4 = prob[i], h4 = ht[i], v4 = vm[i];
        float4 wp4 = wprob[i], wh4 = wht[i], wv4 = wvm[i];
        #pragma unroll
        for (int q = 0; q < 4; q++) {
            float p = ((const float*)&p4)[q], h = ((const float*)&h4)[q], v = ((const float*)&v4)[q];
            float pi = (h == 1.0f) ? 1.f : 0.f;
            float ni = (h < 1.0f) ? 1.f : 0.f;
            float nw = (1.f - h) * (1.f - h); nw *= nw;
            vals[0] += logf(p + 1e-7f) * (1.f - p) * (1.f - p) * pi * v;
            vals[1] += logf(1.f - p + 1e-7f) * p * p * nw * ni * v;
            vals[2] += pi;
            float wp = ((const float*)&wp4)[q], wh = ((const float*)&wh4)[q], wv = ((const float*)&wv4)[q];
            float wpi = (wh == 1.0f) ? 1.f : 0.f;
            float wni = (wh < 1.0f) ? 1.f : 0.f;
            float wnw = (1.f - wh) * (1.f - wh); wnw *= wnw;
            vals[3] += logf(wp + 1e-7f) * (1.f - wp) * (1.f - wp) * wpi * wv;
            vals[4] += logf(1.f - wp + 1e-7f) * wp * wp * wnw * wni * wv;
            vals[5] += wpi;
            vals[6] += wv;
        }
    }
    __shared__ float w[8];
    int lane = threadIdx.x & 31, warp = threadIdx.x >> 5;
    for (int q = 0; q < 7; q++) {
        float v = warpsum(vals[q]);
        if (lane == 0) w[warp] = v;
        __syncthreads();
        if (threadIdx.x == 0) {
            float s = 0;
            for (int u = 0; u < (int)(blockDim.x >> 5); u++) s += w[u];
            atomicAdd(&g_acc[q], (double)s);
        }
        __syncthreads();
    }
}

// ---------------- descriptor normalize + transpose (fp32 -> fp16), both tensors ----------------
__global__ void normdesc_kernel(const float* __restrict__ src0, __half* __restrict__ dst0,
                                const float* __restrict__ src1, __half* __restrict__ dst1) {
    __shared__ float tile[DD][33];
    __shared__ float part[16][32];
    __shared__ float inv[32];
    int which = blockIdx.x >= BB * (NN / 32);
    int blk = blockIdx.x - which * BB * (NN / 32);
    const float* src = which ? src1 : src0;
    __half* dst = which ? dst1 : dst0;
    int b = blk / (NN / 32);
    int jt = blk % (NN / 32);
    int base = jt * 32;
    const float* s = src + (size_t)b * DD * NN;
    for (int idx = threadIdx.x; idx < DD * 32; idx += 512) {
        int d = idx >> 5, j = idx & 31;
        tile[d][j] = s[d * NN + base + j];
    }
    __syncthreads();
    {
        int j = threadIdx.x & 31, g = threadIdx.x >> 5;
        float acc = 0;
        for (int d = g; d < DD; d += 16) { float v = tile[d][j]; acc += v * v; }
        part[g][j] = acc;
    }
    __syncthreads();
    if (threadIdx.x < 32) {
        float s2 = 0;
        #pragma unroll
        for (int g2 = 0; g2 < 16; g2++) s2 += part[g2][threadIdx.x];
        inv[threadIdx.x] = 1.0f / fmaxf(sqrtf(s2), 1e-12f);
    }
    __syncthreads();
    __half* o = dst + (size_t)b * NN * DD;
    for (int idx = threadIdx.x; idx < 32 * DD; idx += 512) {
        int jj = idx >> 8, d = idx & 255;
        o[(size_t)(base + jj) * DD + d] = __float2half_rn(tile[d][jj] * inv[jj]);
    }
}

// ---------------- warped coords + downsampled masks ----------------
__device__ __forceinline__ float bilinear_ds(const float* __restrict__ img, int i, int j) {
    float sr = (i + 0.5f) * ((float)HH / HC) - 0.5f;
    sr = fminf(fmaxf(sr, 0.f), (float)(HH - 1));
    int r0 = (int)floorf(sr); int r1 = min(r0 + 1, HH - 1); float wr = sr - (float)r0;
    float sc = (j + 0.5f) * ((float)WW / WC) - 0.5f;
    sc = fminf(fmaxf(sc, 0.f), (float)(WW - 1));
    int c0 = (int)floorf(sc); int c1 = min(c0 + 1, WW - 1); float wc = sc - (float)c0;
    float a = img[r0 * WW + c0] * (1.f - wr) + img[r1 * WW + c0] * wr;
    float b = img[r0 * WW + c1] * (1.f - wr) + img[r1 * WW + c1] * wr;
    return a * (1.f - wc) + b * wc;
}

__global__ void coords_kernel(const float* __restrict__ vm,
                              const float* __restrict__ wvm,
                              const float* __restrict__ Hm) {
    int idx = blockIdx.x * blockDim.x + threadIdx.x;
    if (idx >= BB * NN) return;
    int b = idx / NN, ij = idx % NN;
    int i = ij / WC, j = ij % WC;
    float y = (float)(i * 8 + 4), x = (float)(j * 8 + 4);
    const float* Hb = Hm + b * 9;
    float w0 = Hb[0] * x + Hb[1] * y + Hb[2];
    float w1 = Hb[3] * x + Hb[4] * y + Hb[5];
    float w2 = Hb[6] * x + Hb[7] * y + Hb[8];
    float vmc  = (bilinear_ds(vm  + (size_t)b * HH * WW, i, j) > 0.5f) ? 1.f : 0.f;
    float wvmc = (bilinear_ds(wvm + (size_t)b * HH * WW, i, j) > 0.5f) ? 1.f : 0.f;
    g_rowgeo[idx] = make_float4(w1 / w2, w0 / w2, vmc, 0.f);
    g_colgeo[idx] = make_float4(y, x, wvmc, 0.f);
}

// ---------------- main: fp16 mma.sync GEMM, 512 thr, 32x32 warp tiles, 2 CTAs/SM ----------------
#define TILE 128
#define KC 32
#define ASTR 40                       // halfs/row: 64B data + 16B pad; conflict-free ldmatrix
#define ABYTES (TILE * ASTR * 2)      // 10240
#define NCHUNK (DD / KC)              // 8

__device__ __forceinline__ float lossterm(float acc, float4 r, float4 c) {
    float dot = fmaxf(acc, 0.f);
    float pd = fmaxf(1.0f - dot, 0.f);
    float nd = fmaxf(dot - 0.2f, 0.f);
    float dy = c.x - r.x, dx = c.y - r.y;
    float d2 = dy * dy + dx * dx;
    float w = r.z * c.z;
    return (d2 <= 56.25f) ? 250.f * pd * w : nd * w;   // (CELL-0.5)^2 = 56.25
}

__global__ __launch_bounds__(512, 2) void gemm_loss_kernel() {
    __shared__ __align__(16) __half As[2][TILE * ASTR];   // 2 x 10 KB
    __shared__ __align__(16) __half Bs[2][TILE * ASTR];   // 2 x 10 KB
    __shared__ float4 s_row[TILE], s_col[TILE];
    __shared__ float wred[16];

    int b = blockIdx.z;
    int i0 = blockIdx.y * TILE;
    int j0 = blockIdx.x * TILE;
    int tid = threadIdx.x;
    int wid = tid >> 5, lane = tid & 31;

    if (tid < TILE) {
        int r = i0 + tid;
        s_row[tid] = (r < NN) ? g_rowgeo[b * NN + r] : make_float4(0.f, 0.f, 0.f, 0.f);
    } else if (tid < 2 * TILE) {
        int t = tid - TILE;
        int c = j0 + t;
        s_col[t] = (c < NN) ? g_colgeo[b * NN + c] : make_float4(0.f, 0.f, 0.f, 0.f);
    }

    const char* A  = (const char*)(g_dnorm  + (size_t)b * NN * DD);
    const char* Bm = (const char*)(g_wdnorm + (size_t)b * NN * DD);

    // cp.async geometry: each chunk row = 64B = 4 x 16B segs; 128 rows x 4 = 512 segs
    // per matrix; 512 threads -> 1 seg of A and 1 of B each.
    int rowT = tid >> 2, colb = (tid & 3) * 16;
    uint32_t okA = (i0 + rowT < NN) ? 16u : 0u;
    uint32_t okB = (j0 + rowT < NN) ? 16u : 0u;
    const char* gA = A  + (size_t)(i0 + rowT) * (DD * 2) + colb;
    const char* gB = Bm + (size_t)(j0 + rowT) * (DD * 2) + colb;
    uint32_t sA = smem_u32(As) + rowT * (ASTR * 2) + colb;
    uint32_t sB = smem_u32(Bs) + rowT * (ASTR * 2) + colb;

    // 16 warps: 4x4 grid of 32x32 warp tiles
    int m_base = (wid >> 2) * 32;     // 0,32,64,96
    int n_base = (wid & 3) * 32;      // 0,32,64,96
    int g = lane >> 3, lr = lane & 7;

    uint32_t acc[2][4][2];            // fp16x2 accumulators: mt x nt x 2
    #pragma unroll
    for (int i = 0; i < 2; i++)
        #pragma unroll
        for (int j = 0; j < 4; j++) { acc[i][j][0] = 0u; acc[i][j][1] = 0u; }

    uint32_t As_base = smem_u32(As), Bs_base = smem_u32(Bs);
    uint32_t a_row_off = (uint32_t)((m_base + (g & 1) * 8 + lr) * ASTR + (g >> 1) * 8) * 2;
    uint32_t b_row_off = (uint32_t)((n_base + (g >> 1) * 8 + lr) * ASTR + (g & 1) * 8) * 2;

    // prologue: chunk 0 -> stage 0
    cp_async16(sA, gA, okA);
    cp_async16(sB, gB, okB);
    CP_COMMIT();

    #pragma unroll
    for (int ck = 0; ck < NCHUNK; ck++) {
        int s = ck & 1;
        CP_WAIT(0);          // chunk ck's copy complete
        __syncthreads();     // stage s readable; all reads of stage 1-s finished
        if (ck + 1 < NCHUNK) {
            uint32_t so = (uint32_t)((ck + 1) & 1) * ABYTES;
            int go = (ck + 1) * (KC * 2);
            cp_async16(sA + so, gA + go, okA);
            cp_async16(sB + so, gB + go, okB);
            CP_COMMIT();
        }

        uint32_t abase = As_base + s * (uint32_t)ABYTES + a_row_off;
        uint32_t bbase = Bs_base + s * (uint32_t)ABYTES + b_row_off;
        #pragma unroll
        for (int ks = 0; ks < KC; ks += 16) {
            uint32_t af[2][4], bf[2][4];
            #pragma unroll
            for (int mt = 0; mt < 2; mt++) {
                uint32_t addr = abase + (uint32_t)(mt * 16 * ASTR + ks) * 2;
                asm volatile("ldmatrix.sync.aligned.m8n8.x4.shared.b16 {%0,%1,%2,%3}, [%4];"
                             : "=r"(af[mt][0]), "=r"(af[mt][1]), "=r"(af[mt][2]), "=r"(af[mt][3])
                             : "r"(addr));
            }
            #pragma unroll
            for (int np = 0; np < 2; np++) {
                uint32_t addr = bbase + (uint32_t)(np * 16 * ASTR + ks) * 2;
                asm volatile("ldmatrix.sync.aligned.m8n8.x4.shared.b16 {%0,%1,%2,%3}, [%4];"
                             : "=r"(bf[np][0]), "=r"(bf[np][1]), "=r"(bf[np][2]), "=r"(bf[np][3])
                             : "r"(addr));
            }
            #pragma unroll
            for (int np = 0; np < 2; np++)
                #pragma unroll
                for (int h = 0; h < 2; h++) {
                    int nt = np * 2 + h;
                    #pragma unroll
                    for (int mt = 0; mt < 2; mt++) {
                        asm volatile(
                            "mma.sync.aligned.m16n8k16.row.col.f16.f16.f16.f16 "
                            "{%0,%1}, {%2,%3,%4,%5}, {%6,%7}, {%0,%1};"
                            : "+r"(acc[mt][nt][0]), "+r"(acc[mt][nt][1])
                            : "r"(af[mt][0]), "r"(af[mt][1]), "r"(af[mt][2]), "r"(af[mt][3]),
                              "r"(bf[np][h * 2]), "r"(bf[np][h * 2 + 1]));
                    }
                }
        }
    }

    // fused epilogue (unpack half2 accumulators)
    int qr = lane >> 2, qc = (lane & 3) * 2;
    float lsum = 0.f;
    #pragma unroll
    for (int mt = 0; mt < 2; mt++) {
        float4 r0 = s_row[m_base + mt * 16 + qr];
        float4 r1 = s_row[m_base + mt * 16 + qr + 8];
        #pragma unroll
        for (int nt = 0; nt < 4; nt++) {
            float4 c0 = s_col[n_base + nt * 8 + qc];
            float4 c1 = s_col[n_base + nt * 8 + qc + 1];
            float2 d0 = __half22float2(*(__half2*)&acc[mt][nt][0]);
            float2 d1 = __half22float2(*(__half2*)&acc[mt][nt][1]);
            lsum += lossterm(d0.x, r0, c0);
            lsum += lossterm(d0.y, r0, c1);
            lsum += lossterm(d1.x, r1, c0);
            lsum += lossterm(d1.y, r1, c1);
        }
    }

    float v = warpsum(lsum);
    if (lane == 0) wred[wid] = v;
    __syncthreads();
    if (tid == 0) {
        float s = 0;
        #pragma unroll
        for (int u = 0; u < 16; u++) s += wred[u];
        atomicAdd(&g_acc[7], (double)s);
    }
}

// ---------------- finalize (also re-zeros accumulators for next replay) ----------------
__global__ void finalize_kernel(float* __restrict__ out) {
    double np1 = g_acc[2];
    double pl  = (np1 == 0.0) ? -g_acc[1] : -(g_acc[0] + g_acc[1]) / fmax(np1, 1.0);
    double np2 = g_acc[5];
    double wpl = (np2 == 0.0) ? -g_acc[4] : -(g_acc[3] + g_acc[4]) / fmax(np2, 1.0);
    double dl  = g_acc[7] / g_acc[6];
    out[0] = (float)(pl + wpl + 1e-4 * dl);
    out[1] = (float)pl;
    out[2] = (float)wpl;
    out[3] = (float)dl;
    #pragma unroll
    for (int q = 0; q < 8; q++) g_acc[q] = 0.0;
}

// ---------------- launch ----------------
extern "C" void kernel_launch(void* const* d_in, const int* in_sizes, int n_in,
                              void* d_out, int out_size) {
    const float* prob  = (const float*)d_in[0];
    const float* ht    = (const float*)d_in[1];
    const float* vm    = (const float*)d_in[2];
    const float* wprob = (const float*)d_in[3];
    const float* wht   = (const float*)d_in[4];
    const float* wvm   = (const float*)d_in[5];
    const float* desc  = (const float*)d_in[6];
    const float* wdesc = (const float*)d_in[7];
    const float* Hm    = (const float*)d_in[8];
    float* out = (float*)d_out;

    detector_kernel<<<600, 256>>>((const float4*)prob, (const float4*)ht, (const float4*)vm,
                                  (const float4*)wprob, (const float4*)wht, (const float4*)wvm);

    __half* dnorm;  cudaGetSymbolAddress((void**)&dnorm,  g_dnorm);
    __half* wdnorm; cudaGetSymbolAddress((void**)&wdnorm, g_wdnorm);
    normdesc_kernel<<<2 * BB * (NN / 32), 512>>>(desc, dnorm, wdesc, wdnorm);

    coords_kernel<<<(BB * NN + 255) / 256, 256>>>(vm, wvm, Hm);

    dim3 grid((NN + TILE - 1) / TILE, (NN + TILE - 1) / TILE, BB);
    gemm_loss_kernel<<<grid, 512>>>();

    finalize_kernel<<<1, 1>>>(out);
}

// round 12
// speedup vs baseline: 1.3110x; 1.3110x over previous
#include <cuda_runtime.h>
#include <cuda_fp16.h>
#include <math.h>
#include <stdint.h>

#define BB 2
#define HH 480
#define WW 640
#define DD 256
#define HC 60
#define WC 80
#define NN 4800          // HC*WC
#define TOTAL_PIX (BB*HH*WW)

// ---------------- device scratch ----------------
// acc: 0 pos1, 1 neg1, 2 npos1, 3 pos2, 4 neg2, 5 npos2, 6 normalization, 7 desc_sum
__device__ double g_acc[8];   // static zero-init; finalize re-zeros after each use
__device__ __align__(16) signed char g_dnorm[BB*NN*DD];   // (b, ij, d) int8 normalized*127
__device__ __align__(16) signed char g_wdnorm[BB*NN*DD];
__device__ float4 g_rowgeo[BB*NN];   // {wy, wx, vm_c, 0}
__device__ float4 g_colgeo[BB*NN];   // {cy, cx, wvm_c, 0}

// ---------------- helpers ----------------
__device__ __forceinline__ float warpsum(float v) {
    #pragma unroll
    for (int o = 16; o; o >>= 1) v += __shfl_down_sync(0xffffffffu, v, o);
    return v;
}

__device__ __forceinline__ uint32_t smem_u32(const void* p) {
    uint32_t a;
    asm("{ .reg .u64 t; cvta.to.shared.u64 t, %1; cvt.u32.u64 %0, t; }" : "=r"(a) : "l"(p));
    return a;
}

__device__ __forceinline__ void cp_async16(uint32_t dst, const void* src, uint32_t bytes) {
    asm volatile("cp.async.cg.shared.global [%0], [%1], 16, %2;"
                 :: "r"(dst), "l"(src), "r"(bytes) : "memory");
}
#define CP_COMMIT() asm volatile("cp.async.commit_group;" ::: "memory")
#define CP_WAIT(n)  asm volatile("cp.async.wait_group %0;" :: "n"(n) : "memory")

// ---------------- detector losses + normalization sum (float4) ----------------
__global__ void detector_kernel(const float4* __restrict__ prob,
                                const float4* __restrict__ ht,
                                const float4* __restrict__ vm,
                                const float4* __restrict__ wprob,
                                const float4* __restrict__ wht,
                                const float4* __restrict__ wvm) {
    float vals[7] = {0, 0, 0, 0, 0, 0, 0};
    const int n4 = TOTAL_PIX / 4;
    for (int i = blockIdx.x * blockDim.x + threadIdx.x; i < n4;
         i += gridDim.x * blockDim.x) {
        float4 p4 = prob[i], h4 = ht[i], v4 = vm[i];
        float4 wp4 = wprob[i], wh4 = wht[i], wv4 = wvm[i];
        #pragma unroll
        for (int q = 0; q < 4; q++) {
            float p = ((const float*)&p4)[q], h = ((const float*)&h4)[q], v = ((const float*)&v4)[q];
            float pi = (h == 1.0f) ? 1.f : 0.f;
            float ni = (h < 1.0f) ? 1.f : 0.f;
            float nw = (1.f - h) * (1.f - h); nw *= nw;
            vals[0] += logf(p + 1e-7f) * (1.f - p) * (1.f - p) * pi * v;
            vals[1] += logf(1.f - p + 1e-7f) * p * p * nw * ni * v;
            vals[2] += pi;
            float wp = ((const float*)&wp4)[q], wh = ((const float*)&wh4)[q], wv = ((const float*)&wv4)[q];
            float wpi = (wh == 1.0f) ? 1.f : 0.f;
            float wni = (wh < 1.0f) ? 1.f : 0.f;
            float wnw = (1.f - wh) * (1.f - wh); wnw *= wnw;
            vals[3] += logf(wp + 1e-7f) * (1.f - wp) * (1.f - wp) * wpi * wv;
            vals[4] += logf(1.f - wp + 1e-7f) * wp * wp * wnw * wni * wv;
            vals[5] += wpi;
            vals[6] += wv;
        }
    }
    __shared__ float w[8];
    int lane = threadIdx.x & 31, warp = threadIdx.x >> 5;
    for (int q = 0; q < 7; q++) {
        float v = warpsum(vals[q]);
        if (lane == 0) w[warp] = v;
        __syncthreads();
        if (threadIdx.x == 0) {
            float s = 0;
            for (int u = 0; u < (int)(blockDim.x >> 5); u++) s += w[u];
            atomicAdd(&g_acc[q], (double)s);
        }
        __syncthreads();
    }
}

// ---------------- descriptor normalize + transpose (fp32 -> int8*127), both tensors ----------------
__global__ void normdesc_kernel(const float* __restrict__ src0, signed char* __restrict__ dst0,
                                const float* __restrict__ src1, signed char* __restrict__ dst1) {
    __shared__ float tile[DD][33];
    __shared__ float part[16][32];
    __shared__ float inv[32];
    int which = blockIdx.x >= BB * (NN / 32);
    int blk = blockIdx.x - which * BB * (NN / 32);
    const float* src = which ? src1 : src0;
    signed char* dst = which ? dst1 : dst0;
    int b = blk / (NN / 32);
    int jt = blk % (NN / 32);
    int base = jt * 32;
    const float* s = src + (size_t)b * DD * NN;
    for (int idx = threadIdx.x; idx < DD * 32; idx += 512) {
        int d = idx >> 5, j = idx & 31;
        tile[d][j] = s[d * NN + base + j];
    }
    __syncthreads();
    {
        int j = threadIdx.x & 31, g = threadIdx.x >> 5;
        float acc = 0;
        for (int d = g; d < DD; d += 16) { float v = tile[d][j]; acc += v * v; }
        part[g][j] = acc;
    }
    __syncthreads();
    if (threadIdx.x < 32) {
        float s2 = 0;
        #pragma unroll
        for (int g2 = 0; g2 < 16; g2++) s2 += part[g2][threadIdx.x];
        inv[threadIdx.x] = 127.0f / fmaxf(sqrtf(s2), 1e-12f);
    }
    __syncthreads();
    signed char* o = dst + (size_t)b * NN * DD;
    for (int idx = threadIdx.x; idx < 32 * DD; idx += 512) {
        int jj = idx >> 8, d = idx & 255;
        int q = __float2int_rn(tile[d][jj] * inv[jj]);
        q = max(-127, min(127, q));
        o[(size_t)(base + jj) * DD + d] = (signed char)q;
    }
}

// ---------------- warped coords + downsampled masks ----------------
__device__ __forceinline__ float bilinear_ds(const float* __restrict__ img, int i, int j) {
    float sr = (i + 0.5f) * ((float)HH / HC) - 0.5f;
    sr = fminf(fmaxf(sr, 0.f), (float)(HH - 1));
    int r0 = (int)floorf(sr); int r1 = min(r0 + 1, HH - 1); float wr = sr - (float)r0;
    float sc = (j + 0.5f) * ((float)WW / WC) - 0.5f;
    sc = fminf(fmaxf(sc, 0.f), (float)(WW - 1));
    int c0 = (int)floorf(sc); int c1 = min(c0 + 1, WW - 1); float wc = sc - (float)c0;
    float a = img[r0 * WW + c0] * (1.f - wr) + img[r1 * WW + c0] * wr;
    float b = img[r0 * WW + c1] * (1.f - wr) + img[r1 * WW + c1] * wr;
    return a * (1.f - wc) + b * wc;
}

__global__ void coords_kernel(const float* __restrict__ vm,
                              const float* __restrict__ wvm,
                              const float* __restrict__ Hm) {
    int idx = blockIdx.x * blockDim.x + threadIdx.x;
    if (idx >= BB * NN) return;
    int b = idx / NN, ij = idx % NN;
    int i = ij / WC, j = ij % WC;
    float y = (float)(i * 8 + 4), x = (float)(j * 8 + 4);
    const float* Hb = Hm + b * 9;
    float w0 = Hb[0] * x + Hb[1] * y + Hb[2];
    float w1 = Hb[3] * x + Hb[4] * y + Hb[5];
    float w2 = Hb[6] * x + Hb[7] * y + Hb[8];
    float vmc  = (bilinear_ds(vm  + (size_t)b * HH * WW, i, j) > 0.5f) ? 1.f : 0.f;
    float wvmc = (bilinear_ds(wvm + (size_t)b * HH * WW, i, j) > 0.5f) ? 1.f : 0.f;
    g_rowgeo[idx] = make_float4(w1 / w2, w0 / w2, vmc, 0.f);
    g_colgeo[idx] = make_float4(y, x, wvmc, 0.f);
}

// ---------------- main: int8 IMMA GEMM, 96x128 tiles, 384 thr, 2 CTAs/SM ----------------
#define TM 96
#define TN 128
#define ASTRB 80                      // bytes/row: 64B data + 16B pad (same swizzle as fp16 path)
#define A_STAGE (TM * ASTRB)          // 7680
#define B_STAGE (TN * ASTRB)          // 10240
#define NCH 4                         // chunks of 64B over K=256B
#define INV127SQ (1.0f / 16129.0f)

__device__ __forceinline__ float lossterm(float dotv, float4 r, float4 c) {
    float dot = fmaxf(dotv, 0.f);
    float pd = fmaxf(1.0f - dot, 0.f);
    float nd = fmaxf(dot - 0.2f, 0.f);
    float dy = c.x - r.x, dx = c.y - r.y;
    float d2 = dy * dy + dx * dx;
    float w = r.z * c.z;
    return (d2 <= 56.25f) ? 250.f * pd * w : nd * w;   // (CELL-0.5)^2 = 56.25
}

__global__ __launch_bounds__(384, 2) void gemm_loss_kernel() {
    __shared__ __align__(16) char As[2][A_STAGE];
    __shared__ __align__(16) char Bs[2][B_STAGE];
    __shared__ float4 s_row[TM], s_col[TN];
    __shared__ float wred[12];

    int b = blockIdx.z;
    int i0 = blockIdx.y * TM;    // always full: 50*96 = 4800
    int j0 = blockIdx.x * TN;
    int tid = threadIdx.x;
    int wid = tid >> 5, lane = tid & 31;

    if (tid < TM) {
        s_row[tid] = g_rowgeo[b * NN + i0 + tid];
    } else if (tid >= 128 && tid < 128 + TN) {
        int t = tid - 128;
        int c = j0 + t;
        s_col[t] = (c < NN) ? g_colgeo[b * NN + c] : make_float4(0.f, 0.f, 0.f, 0.f);
    }

    const char* A  = (const char*)g_dnorm  + (size_t)b * NN * DD;
    const char* Bm = (const char*)g_wdnorm + (size_t)b * NN * DD;

    // cp.async geometry: chunk row = 64B = 4 x 16B segs.
    // A: 96 rows x 4 = 384 segs -> 1/thread. B: 128 rows x 4 = 512 segs -> 1/thread + extra for tid<128.
    int rowA = tid >> 2, colA = (tid & 3) * 16;
    const char* gA = A + (size_t)(i0 + rowA) * DD + colA;
    uint32_t sA = smem_u32(As) + rowA * ASTRB + colA;

    int rowB0 = tid >> 2, colB0 = (tid & 3) * 16;
    uint32_t okB0 = (j0 + rowB0 < NN) ? 16u : 0u;
    const char* gB0 = Bm + (size_t)(j0 + rowB0) * DD + colB0;
    uint32_t sB0 = smem_u32(Bs) + rowB0 * ASTRB + colB0;
    int rowB1 = 96 + (tid >> 2);
    uint32_t okB1 = (tid < 128 && j0 + rowB1 < NN) ? 16u : 0u;
    const char* gB1 = Bm + (size_t)(j0 + rowB1) * DD + colB0;
    uint32_t sB1 = smem_u32(Bs) + rowB1 * ASTRB + colB0;

    // 12 warps: 3(m) x 4(n) grid of 32x32 warp tiles
    int m_base = (wid >> 2) * 32;     // 0,32,64
    int n_base = (wid & 3) * 32;      // 0,32,64,96
    int g = lane >> 3, lr = lane & 7;

    int acc[2][4][4];                 // s32 accumulators: mt x nt x 4
    #pragma unroll
    for (int i = 0; i < 2; i++)
        #pragma unroll
        for (int j = 0; j < 4; j++)
            #pragma unroll
            for (int q = 0; q < 4; q++) acc[i][j][q] = 0;

    uint32_t As_base = smem_u32(As), Bs_base = smem_u32(Bs);
    uint32_t a_row_off = (uint32_t)((m_base + (g & 1) * 8 + lr) * ASTRB + (g >> 1) * 16);
    uint32_t b_row_off = (uint32_t)((n_base + (g >> 1) * 8 + lr) * ASTRB + (g & 1) * 16);

    // prologue: chunk 0 -> stage 0
    cp_async16(sA, gA, 16u);
    cp_async16(sB0, gB0, okB0);
    if (tid < 128) cp_async16(sB1, gB1, okB1);
    CP_COMMIT();

    #pragma unroll
    for (int ck = 0; ck < NCH; ck++) {
        int s = ck & 1;
        CP_WAIT(0);          // chunk ck's copy complete
        __syncthreads();     // stage s readable; all reads of stage 1-s finished
        if (ck + 1 < NCH) {
            int sn = (ck + 1) & 1;
            int go = (ck + 1) * 64;
            cp_async16(sA + sn * A_STAGE, gA + go, 16u);
            cp_async16(sB0 + sn * B_STAGE, gB0 + go, okB0);
            if (tid < 128) cp_async16(sB1 + sn * B_STAGE, gB1 + go, okB1);
            CP_COMMIT();
        }

        uint32_t abase = As_base + s * (uint32_t)A_STAGE + a_row_off;
        uint32_t bbase = Bs_base + s * (uint32_t)B_STAGE + b_row_off;
        #pragma unroll
        for (int ksB = 0; ksB < 64; ksB += 32) {
            uint32_t af[2][4], bf[2][4];
            #pragma unroll
            for (int mt = 0; mt < 2; mt++) {
                uint32_t addr = abase + (uint32_t)(mt * 16 * ASTRB + ksB);
                asm volatile("ldmatrix.sync.aligned.m8n8.x4.shared.b16 {%0,%1,%2,%3}, [%4];"
                             : "=r"(af[mt][0]), "=r"(af[mt][1]), "=r"(af[mt][2]), "=r"(af[mt][3])
                             : "r"(addr));
            }
            #pragma unroll
            for (int np = 0; np < 2; np++) {
                uint32_t addr = bbase + (uint32_t)(np * 16 * ASTRB + ksB);
                asm volatile("ldmatrix.sync.aligned.m8n8.x4.shared.b16 {%0,%1,%2,%3}, [%4];"
                             : "=r"(bf[np][0]), "=r"(bf[np][1]), "=r"(bf[np][2]), "=r"(bf[np][3])
                             : "r"(addr));
            }
            #pragma unroll
            for (int np = 0; np < 2; np++)
                #pragma unroll
                for (int h = 0; h < 2; h++) {
                    int nt = np * 2 + h;
                    #pragma unroll
                    for (int mt = 0; mt < 2; mt++) {
                        asm volatile(
                            "mma.sync.aligned.m16n8k32.row.col.s32.s8.s8.s32 "
                            "{%0,%1,%2,%3}, {%4,%5,%6,%7}, {%8,%9}, {%0,%1,%2,%3};"
                            : "+r"(acc[mt][nt][0]), "+r"(acc[mt][nt][1]),
                              "+r"(acc[mt][nt][2]), "+r"(acc[mt][nt][3])
                            : "r"(af[mt][0]), "r"(af[mt][1]), "r"(af[mt][2]), "r"(af[mt][3]),
                              "r"(bf[np][h * 2]), "r"(bf[np][h * 2 + 1]));
                    }
                }
        }
    }

    // fused epilogue: c0=(qr,qc), c1=(qr,qc+1), c2=(qr+8,qc), c3=(qr+8,qc+1)
    int qr = lane >> 2, qc = (lane & 3) * 2;
    float lsum = 0.f;
    #pragma unroll
    for (int mt = 0; mt < 2; mt++) {
        float4 r0 = s_row[m_base + mt * 16 + qr];
        float4 r1 = s_row[m_base + mt * 16 + qr + 8];
        #pragma unroll
        for (int nt = 0; nt < 4; nt++) {
            float4 c0 = s_col[n_base + nt * 8 + qc];
            float4 c1 = s_col[n_base + nt * 8 + qc + 1];
            lsum += lossterm((float)acc[mt][nt][0] * INV127SQ, r0, c0);
            lsum += lossterm((float)acc[mt][nt][1] * INV127SQ, r0, c1);
            lsum += lossterm((float)acc[mt][nt][2] * INV127SQ, r1, c0);
            lsum += lossterm((float)acc[mt][nt][3] * INV127SQ, r1, c1);
        }
    }

    float v = warpsum(lsum);
    if (lane == 0) wred[wid] = v;
    __syncthreads();
    if (tid == 0) {
        float s = 0;
        #pragma unroll
        for (int u = 0; u < 12; u++) s += wred[u];
        atomicAdd(&g_acc[7], (double)s);
    }
}

// ---------------- finalize (also re-zeros accumulators for next replay) ----------------
__global__ void finalize_kernel(float* __restrict__ out) {
    double np1 = g_acc[2];
    double pl  = (np1 == 0.0) ? -g_acc[1] : -(g_acc[0] + g_acc[1]) / fmax(np1, 1.0);
    double np2 = g_acc[5];
    double wpl = (np2 == 0.0) ? -g_acc[4] : -(g_acc[3] + g_acc[4]) / fmax(np2, 1.0);
    double dl  = g_acc[7] / g_acc[6];
    out[0] = (float)(pl + wpl + 1e-4 * dl);
    out[1] = (float)pl;
    out[2] = (float)wpl;
    out[3] = (float)dl;
    #pragma unroll
    for (int q = 0; q < 8; q++) g_acc[q] = 0.0;
}

// ---------------- launch ----------------
extern "C" void kernel_launch(void* const* d_in, const int* in_sizes, int n_in,
                              void* d_out, int out_size) {
    const float* prob  = (const float*)d_in[0];
    const float* ht    = (const float*)d_in[1];
    const float* vm    = (const float*)d_in[2];
    const float* wprob = (const float*)d_in[3];
    const float* wht   = (const float*)d_in[4];
    const float* wvm   = (const float*)d_in[5];
    const float* desc  = (const float*)d_in[6];
    const float* wdesc = (const float*)d_in[7];
    const float* Hm    = (const float*)d_in[8];
    float* out = (float*)d_out;

    detector_kernel<<<600, 256>>>((const float4*)prob, (const float4*)ht, (const float4*)vm,
                                  (const float4*)wprob, (const float4*)wht, (const float4*)wvm);

    signed char* dnorm;  cudaGetSymbolAddress((void**)&dnorm,  g_dnorm);
    signed char* wdnorm; cudaGetSymbolAddress((void**)&wdnorm, g_wdnorm);
    normdesc_kernel<<<2 * BB * (NN / 32), 512>>>(desc, dnorm, wdesc, wdnorm);

    coords_kernel<<<(BB * NN + 255) / 256, 256>>>(vm, wvm, Hm);

    dim3 grid((NN + TN - 1) / TN, NN / TM, BB);
    gemm_loss_kernel<<<grid, 384>>>();

    finalize_kernel<<<1, 1>>>(out);
}

// round 13
// speedup vs baseline: 1.4840x; 1.1319x over previous
#include <cuda_runtime.h>
#include <math.h>
#include <stdint.h>

#define BB 2
#define HH 480
#define WW 640
#define DD 256
#define HC 60
#define WC 80
#define NN 4800          // HC*WC
#define TOTAL_PIX (BB*HH*WW)

// ---------------- device scratch ----------------
// acc: 0 pos1, 1 neg1, 2 npos1, 3 pos2, 4 neg2, 5 npos2, 6 normalization, 7 desc_sum
__device__ double g_acc[8];   // static zero-init; finalize re-zeros after each use
__device__ __align__(16) signed char g_dnorm[BB*NN*DD];   // (b, ij, d) int8 normalized*127
__device__ __align__(16) signed char g_wdnorm[BB*NN*DD];
__device__ float4 g_rowgeo[BB*NN];   // {wy, wx, vm_c, 0}
__device__ float4 g_colgeo[BB*NN];   // {cy, cx, wvm_c, 0}

// ---------------- helpers ----------------
__device__ __forceinline__ float warpsum(float v) {
    #pragma unroll
    for (int o = 16; o; o >>= 1) v += __shfl_down_sync(0xffffffffu, v, o);
    return v;
}

__device__ __forceinline__ uint32_t smem_u32(const void* p) {
    uint32_t a;
    asm("{ .reg .u64 t; cvta.to.shared.u64 t, %1; cvt.u32.u64 %0, t; }" : "=r"(a) : "l"(p));
    return a;
}

__device__ __forceinline__ void cp_async16(uint32_t dst, const void* src, uint32_t bytes) {
    asm volatile("cp.async.cg.shared.global [%0], [%1], 16, %2;"
                 :: "r"(dst), "l"(src), "r"(bytes) : "memory");
}
#define CP_COMMIT() asm volatile("cp.async.commit_group;" ::: "memory")
#define CP_WAIT(n)  asm volatile("cp.async.wait_group %0;" :: "n"(n) : "memory")

// ---------------- fused prep: detector + normdesc + coords ----------------
__device__ __forceinline__ float bilinear_ds(const float* __restrict__ img, int i, int j) {
    float sr = (i + 0.5f) * ((float)HH / HC) - 0.5f;
    sr = fminf(fmaxf(sr, 0.f), (float)(HH - 1));
    int r0 = (int)floorf(sr); int r1 = min(r0 + 1, HH - 1); float wr = sr - (float)r0;
    float sc = (j + 0.5f) * ((float)WW / WC) - 0.5f;
    sc = fminf(fmaxf(sc, 0.f), (float)(WW - 1));
    int c0 = (int)floorf(sc); int c1 = min(c0 + 1, WW - 1); float wc = sc - (float)c0;
    float a = img[r0 * WW + c0] * (1.f - wr) + img[r1 * WW + c0] * wr;
    float b = img[r0 * WW + c1] * (1.f - wr) + img[r1 * WW + c1] * wr;
    return a * (1.f - wc) + b * wc;
}

#define ND_BLOCKS (BB * (NN / 32))        // 300 per tensor, 600 total
#define DET_BLOCKS (TOTAL_PIX / 4 / 512)  // 300
#define CRD_BLOCKS ((BB * NN + 511) / 512) // 19
#define PREP_BLOCKS (2 * ND_BLOCKS + DET_BLOCKS + CRD_BLOCKS)

__global__ __launch_bounds__(512) void prep_kernel(
    const float* __restrict__ prob, const float* __restrict__ ht,
    const float* __restrict__ vm, const float* __restrict__ wprob,
    const float* __restrict__ wht, const float* __restrict__ wvm,
    const float* __restrict__ desc, const float* __restrict__ wdesc,
    const float* __restrict__ Hm,
    signed char* __restrict__ dnorm, signed char* __restrict__ wdnorm)
{
    __shared__ float tile[DD][33];
    __shared__ float part[16][32];
    __shared__ float inv[32];
    __shared__ float w[16];

    int blk = blockIdx.x;
    int tid = threadIdx.x;

    if (blk < 2 * ND_BLOCKS) {
        // ---- descriptor normalize + transpose (fp32 -> int8*127) ----
        int which = blk >= ND_BLOCKS;
        int blk2 = blk - which * ND_BLOCKS;
        const float* src = which ? wdesc : desc;
        signed char* dst = which ? wdnorm : dnorm;
        int b = blk2 / (NN / 32);
        int jt = blk2 % (NN / 32);
        int base = jt * 32;
        const float* s = src + (size_t)b * DD * NN;
        for (int idx = tid; idx < DD * 32; idx += 512) {
            int d = idx >> 5, j = idx & 31;
            tile[d][j] = s[d * NN + base + j];
        }
        __syncthreads();
        {
            int j = tid & 31, g = tid >> 5;
            float acc = 0;
            for (int d = g; d < DD; d += 16) { float v = tile[d][j]; acc += v * v; }
            part[g][j] = acc;
        }
        __syncthreads();
        if (tid < 32) {
            float s2 = 0;
            #pragma unroll
            for (int g2 = 0; g2 < 16; g2++) s2 += part[g2][tid];
            inv[tid] = 127.0f / fmaxf(sqrtf(s2), 1e-12f);
        }
        __syncthreads();
        signed char* o = dst + (size_t)b * NN * DD;
        for (int idx = tid; idx < 32 * DD; idx += 512) {
            int jj = idx >> 8, d = idx & 255;
            int q = __float2int_rn(tile[d][jj] * inv[jj]);
            q = max(-127, min(127, q));
            o[(size_t)(base + jj) * DD + d] = (signed char)q;
        }
    } else if (blk < 2 * ND_BLOCKS + DET_BLOCKS) {
        // ---- detector losses + normalization sum ----
        int i = (blk - 2 * ND_BLOCKS) * 512 + tid;   // exactly TOTAL_PIX/4 threads
        float vals[7];
        float4 p4 = ((const float4*)prob)[i], h4 = ((const float4*)ht)[i], v4 = ((const float4*)vm)[i];
        float4 wp4 = ((const float4*)wprob)[i], wh4 = ((const float4*)wht)[i], wv4 = ((const float4*)wvm)[i];
        #pragma unroll
        for (int q = 0; q < 7; q++) vals[q] = 0.f;
        #pragma unroll
        for (int q = 0; q < 4; q++) {
            float p = ((const float*)&p4)[q], h = ((const float*)&h4)[q], v = ((const float*)&v4)[q];
            float pi = (h == 1.0f) ? 1.f : 0.f;
            float ni = (h < 1.0f) ? 1.f : 0.f;
            float nw = (1.f - h) * (1.f - h); nw *= nw;
            vals[0] += logf(p + 1e-7f) * (1.f - p) * (1.f - p) * pi * v;
            vals[1] += logf(1.f - p + 1e-7f) * p * p * nw * ni * v;
            vals[2] += pi;
            float wp = ((const float*)&wp4)[q], wh = ((const float*)&wh4)[q], wv = ((const float*)&wv4)[q];
            float wpi = (wh == 1.0f) ? 1.f : 0.f;
            float wni = (wh < 1.0f) ? 1.f : 0.f;
            float wnw = (1.f - wh) * (1.f - wh); wnw *= wnw;
            vals[3] += logf(wp + 1e-7f) * (1.f - wp) * (1.f - wp) * wpi * wv;
            vals[4] += logf(1.f - wp + 1e-7f) * wp * wp * wnw * wni * wv;
            vals[5] += wpi;
            vals[6] += wv;
        }
        int lane = tid & 31, warp = tid >> 5;
        for (int q = 0; q < 7; q++) {
            float v = warpsum(vals[q]);
            if (lane == 0) w[warp] = v;
            __syncthreads();
            if (tid == 0) {
                float s = 0;
                #pragma unroll
                for (int u = 0; u < 16; u++) s += w[u];
                atomicAdd(&g_acc[q], (double)s);
            }
            __syncthreads();
        }
    } else {
        // ---- warped coords + downsampled masks ----
        int idx = (blk - 2 * ND_BLOCKS - DET_BLOCKS) * 512 + tid;
        if (idx < BB * NN) {
            int b = idx / NN, ij = idx % NN;
            int i = ij / WC, j = ij % WC;
            float y = (float)(i * 8 + 4), x = (float)(j * 8 + 4);
            const float* Hb = Hm + b * 9;
            float w0 = Hb[0] * x + Hb[1] * y + Hb[2];
            float w1 = Hb[3] * x + Hb[4] * y + Hb[5];
            float w2 = Hb[6] * x + Hb[7] * y + Hb[8];
            float vmc  = (bilinear_ds(vm  + (size_t)b * HH * WW, i, j) > 0.5f) ? 1.f : 0.f;
            float wvmc = (bilinear_ds(wvm + (size_t)b * HH * WW, i, j) > 0.5f) ? 1.f : 0.f;
            g_rowgeo[idx] = make_float4(w1 / w2, w0 / w2, vmc, 0.f);
            g_colgeo[idx] = make_float4(y, x, wvmc, 0.f);
        }
    }
}

// ---------------- main: int8 IMMA GEMM, full-K smem, 96x128 tiles, 384 thr ----------------
#define TM 96
#define TN 128
#define ASTRB 272                     // bytes/row: 256B data + 16B pad (17x16B, conflict-free)
#define A_BYTES (TM * ASTRB)          // 26112
#define B_BYTES (TN * ASTRB)          // 34816
#define ROW_OFF (A_BYTES + B_BYTES)   // 60928
#define COL_OFF (ROW_OFF + TM * 16)
#define WRED_OFF (COL_OFF + TN * 16)
#define SMEM_TOTAL (WRED_OFF + 48)
#define INV127SQ (1.0f / 16129.0f)

__device__ __forceinline__ float lossterm(float dotv, float4 r, float4 c) {
    float dot = fmaxf(dotv, 0.f);
    float pd = fmaxf(1.0f - dot, 0.f);
    float nd = fmaxf(dot - 0.2f, 0.f);
    float dy = c.x - r.x, dx = c.y - r.y;
    float d2 = dy * dy + dx * dx;
    float w = r.z * c.z;
    return (d2 <= 56.25f) ? 250.f * pd * w : nd * w;   // (CELL-0.5)^2 = 56.25
}

__global__ __launch_bounds__(384, 2) void gemm_loss_kernel() {
    extern __shared__ __align__(16) char dsm[];
    float4* s_row = (float4*)(dsm + ROW_OFF);
    float4* s_col = (float4*)(dsm + COL_OFF);
    float*  wred  = (float*)(dsm + WRED_OFF);

    int b = blockIdx.z;
    int i0 = blockIdx.y * TM;    // always full: 50*96 = 4800
    int j0 = blockIdx.x * TN;
    int tid = threadIdx.x;
    int wid = tid >> 5, lane = tid & 31;

    const char* A  = (const char*)g_dnorm  + (size_t)b * NN * DD;
    const char* Bm = (const char*)g_wdnorm + (size_t)b * NN * DD;
    uint32_t smem0 = smem_u32(dsm);

    // ---- one-shot tile load: A 96x256B (1536 segs), B 128x256B (2048 segs) ----
    #pragma unroll
    for (int q = 0; q < 4; q++) {
        int seg = tid + q * 384;           // < 1536 always
        int row = seg >> 4, col = (seg & 15) * 16;
        cp_async16(smem0 + row * ASTRB + col, A + (size_t)(i0 + row) * DD + col, 16u);
    }
    #pragma unroll
    for (int q = 0; q < 6; q++) {
        int seg = tid + q * 384;
        if (seg < 2048) {
            int row = seg >> 4, col = (seg & 15) * 16;
            uint32_t ok = (j0 + row < NN) ? 16u : 0u;
            cp_async16(smem0 + A_BYTES + row * ASTRB + col,
                       Bm + (size_t)(j0 + row) * DD + col, ok);
        }
    }
    CP_COMMIT();

    // geometry while the bulk copy flies
    if (tid < TM) {
        s_row[tid] = g_rowgeo[b * NN + i0 + tid];
    } else if (tid >= 128 && tid < 128 + TN) {
        int t = tid - 128;
        int c = j0 + t;
        s_col[t] = (c < NN) ? g_colgeo[b * NN + c] : make_float4(0.f, 0.f, 0.f, 0.f);
    }

    // 12 warps: 3(m) x 4(n) grid of 32x32 warp tiles
    int m_base = (wid >> 2) * 32;     // 0,32,64
    int n_base = (wid & 3) * 32;      // 0,32,64,96
    int g = lane >> 3, lr = lane & 7;

    int acc[2][4][4];
    #pragma unroll
    for (int i = 0; i < 2; i++)
        #pragma unroll
        for (int j = 0; j < 4; j++)
            #pragma unroll
            for (int q = 0; q < 4; q++) acc[i][j][q] = 0;

    uint32_t abase = smem0 + (uint32_t)((m_base + (g & 1) * 8 + lr) * ASTRB + (g >> 1) * 16);
    uint32_t bbase = smem0 + (uint32_t)A_BYTES
                   + (uint32_t)((n_base + (g >> 1) * 8 + lr) * ASTRB + (g & 1) * 16);

    CP_WAIT(0);
    __syncthreads();   // whole tile resident; no further barriers until epilogue

    #pragma unroll
    for (int ks = 0; ks < 8; ks++) {         // K-step = 32 bytes
        uint32_t af[2][4], bf[2][4];
        #pragma unroll
        for (int mt = 0; mt < 2; mt++) {
            uint32_t addr = abase + (uint32_t)(mt * 16 * ASTRB + ks * 32);
            asm volatile("ldmatrix.sync.aligned.m8n8.x4.shared.b16 {%0,%1,%2,%3}, [%4];"
                         : "=r"(af[mt][0]), "=r"(af[mt][1]), "=r"(af[mt][2]), "=r"(af[mt][3])
                         : "r"(addr));
        }
        #pragma unroll
        for (int np = 0; np < 2; np++) {
            uint32_t addr = bbase + (uint32_t)(np * 16 * ASTRB + ks * 32);
            asm volatile("ldmatrix.sync.aligned.m8n8.x4.shared.b16 {%0,%1,%2,%3}, [%4];"
                         : "=r"(bf[np][0]), "=r"(bf[np][1]), "=r"(bf[np][2]), "=r"(bf[np][3])
                         : "r"(addr));
        }
        #pragma unroll
        for (int np = 0; np < 2; np++)
            #pragma unroll
            for (int h = 0; h < 2; h++) {
                int nt = np * 2 + h;
                #pragma unroll
                for (int mt = 0; mt < 2; mt++) {
                    asm volatile(
                        "mma.sync.aligned.m16n8k32.row.col.s32.s8.s8.s32 "
                        "{%0,%1,%2,%3}, {%4,%5,%6,%7}, {%8,%9}, {%0,%1,%2,%3};"
                        : "+r"(acc[mt][nt][0]), "+r"(acc[mt][nt][1]),
                          "+r"(acc[mt][nt][2]), "+r"(acc[mt][nt][3])
                        : "r"(af[mt][0]), "r"(af[mt][1]), "r"(af[mt][2]), "r"(af[mt][3]),
                          "r"(bf[np][h * 2]), "r"(bf[np][h * 2 + 1]));
                }
            }
    }

    // fused epilogue: c0=(qr,qc), c1=(qr,qc+1), c2=(qr+8,qc), c3=(qr+8,qc+1)
    int qr = lane >> 2, qc = (lane & 3) * 2;
    float lsum = 0.f;
    #pragma unroll
    for (int mt = 0; mt < 2; mt++) {
        float4 r0 = s_row[m_base + mt * 16 + qr];
        float4 r1 = s_row[m_base + mt * 16 + qr + 8];
        #pragma unroll
        for (int nt = 0; nt < 4; nt++) {
            float4 c0 = s_col[n_base + nt * 8 + qc];
            float4 c1 = s_col[n_base + nt * 8 + qc + 1];
            lsum += lossterm((float)acc[mt][nt][0] * INV127SQ, r0, c0);
            lsum += lossterm((float)acc[mt][nt][1] * INV127SQ, r0, c1);
            lsum += lossterm((float)acc[mt][nt][2] * INV127SQ, r1, c0);
            lsum += lossterm((float)acc[mt][nt][3] * INV127SQ, r1, c1);
        }
    }

    float v = warpsum(lsum);
    if (lane == 0) wred[wid] = v;
    __syncthreads();
    if (tid == 0) {
        float s = 0;
        #pragma unroll
        for (int u = 0; u < 12; u++) s += wred[u];
        atomicAdd(&g_acc[7], (double)s);
    }
}

// ---------------- finalize (also re-zeros accumulators for next replay) ----------------
__global__ void finalize_kernel(float* __restrict__ out) {
    double np1 = g_acc[2];
    double pl  = (np1 == 0.0) ? -g_acc[1] : -(g_acc[0] + g_acc[1]) / fmax(np1, 1.0);
    double np2 = g_acc[5];
    double wpl = (np2 == 0.0) ? -g_acc[4] : -(g_acc[3] + g_acc[4]) / fmax(np2, 1.0);
    double dl  = g_acc[7] / g_acc[6];
    out[0] = (float)(pl + wpl + 1e-4 * dl);
    out[1] = (float)pl;
    out[2] = (float)wpl;
    out[3] = (float)dl;
    #pragma unroll
    for (int q = 0; q < 8; q++) g_acc[q] = 0.0;
}

// ---------------- launch ----------------
extern "C" void kernel_launch(void* const* d_in, const int* in_sizes, int n_in,
                              void* d_out, int out_size) {
    const float* prob  = (const float*)d_in[0];
    const float* ht    = (const float*)d_in[1];
    const float* vm    = (const float*)d_in[2];
    const float* wprob = (const float*)d_in[3];
    const float* wht   = (const float*)d_in[4];
    const float* wvm   = (const float*)d_in[5];
    const float* desc  = (const float*)d_in[6];
    const float* wdesc = (const float*)d_in[7];
    const float* Hm    = (const float*)d_in[8];
    float* out = (float*)d_out;

    cudaFuncSetAttribute(gemm_loss_kernel,
                         cudaFuncAttributeMaxDynamicSharedMemorySize, SMEM_TOTAL);

    signed char* dnorm;  cudaGetSymbolAddress((void**)&dnorm,  g_dnorm);
    signed char* wdnorm; cudaGetSymbolAddress((void**)&wdnorm, g_wdnorm);

    prep_kernel<<<PREP_BLOCKS, 512>>>(prob, ht, vm, wprob, wht, wvm,
                                      desc, wdesc, Hm, dnorm, wdnorm);

    dim3 grid((NN + TN - 1) / TN, NN / TM, BB);
    gemm_loss_kernel<<<grid, 384, SMEM_TOTAL>>>();

    finalize_kernel<<<1, 1>>>(out);
}

// round 15
// speedup vs baseline: 1.5208x; 1.0248x over previous
#include <cuda_runtime.h>
#include <math.h>
#include <stdint.h>

#define BB 2
#define HH 480
#define WW 640
#define DD 256
#define HC 60
#define WC 80
#define NN 4800          // HC*WC
#define TOTAL_PIX (BB*HH*WW)

// ---------------- device scratch ----------------
// acc: 0 pos1, 1 neg1, 2 npos1, 3 pos2, 4 neg2, 5 npos2, 6 normalization, 7 desc_sum
__device__ double g_acc[8];   // static zero-init; finalize re-zeros after each use
__device__ __align__(16) signed char g_dnorm[BB*NN*DD];   // (b, ij, d) int8 normalized*127
__device__ __align__(16) signed char g_wdnorm[BB*NN*DD];
__device__ float4 g_rowgeo[BB*NN];   // {wy, wx, vm_c, 0}
__device__ float4 g_colgeo[BB*NN];   // {cy, cx, wvm_c, 0}

// ---------------- helpers ----------------
__device__ __forceinline__ float warpsum(float v) {
    #pragma unroll
    for (int o = 16; o; o >>= 1) v += __shfl_down_sync(0xffffffffu, v, o);
    return v;
}

__device__ __forceinline__ uint32_t smem_u32(const void* p) {
    uint32_t a;
    asm("{ .reg .u64 t; cvta.to.shared.u64 t, %1; cvt.u32.u64 %0, t; }" : "=r"(a) : "l"(p));
    return a;
}

__device__ __forceinline__ void cp_async16(uint32_t dst, const void* src, uint32_t bytes) {
    asm volatile("cp.async.cg.shared.global [%0], [%1], 16, %2;"
                 :: "r"(dst), "l"(src), "r"(bytes) : "memory");
}
#define CP_COMMIT() asm volatile("cp.async.commit_group;" ::: "memory")
#define CP_WAIT(n)  asm volatile("cp.async.wait_group %0;" :: "n"(n) : "memory")

// ---------------- fused prep: detector + normdesc + coords ----------------
__device__ __forceinline__ float bilinear_ds(const float* __restrict__ img, int i, int j) {
    float sr = (i + 0.5f) * ((float)HH / HC) - 0.5f;
    sr = fminf(fmaxf(sr, 0.f), (float)(HH - 1));
    int r0 = (int)floorf(sr); int r1 = min(r0 + 1, HH - 1); float wr = sr - (float)r0;
    float sc = (j + 0.5f) * ((float)WW / WC) - 0.5f;
    sc = fminf(fmaxf(sc, 0.f), (float)(WW - 1));
    int c0 = (int)floorf(sc); int c1 = min(c0 + 1, WW - 1); float wc = sc - (float)c0;
    float a = img[r0 * WW + c0] * (1.f - wr) + img[r1 * WW + c0] * wr;
    float b = img[r0 * WW + c1] * (1.f - wr) + img[r1 * WW + c1] * wr;
    return a * (1.f - wc) + b * wc;
}

#define ND_BLOCKS (BB * (NN / 32))        // 300 per tensor, 600 total
#define DET_BLOCKS (TOTAL_PIX / 4 / 512)  // 300
#define CRD_BLOCKS ((BB * NN + 511) / 512) // 19
#define PREP_BLOCKS (2 * ND_BLOCKS + DET_BLOCKS + CRD_BLOCKS)

__global__ __launch_bounds__(512) void prep_kernel(
    const float* __restrict__ prob, const float* __restrict__ ht,
    const float* __restrict__ vm, const float* __restrict__ wprob,
    const float* __restrict__ wht, const float* __restrict__ wvm,
    const float* __restrict__ desc, const float* __restrict__ wdesc,
    const float* __restrict__ Hm,
    signed char* __restrict__ dnorm, signed char* __restrict__ wdnorm)
{
    __shared__ float tile[DD][33];
    __shared__ float part[16][32];
    __shared__ float inv[32];
    __shared__ float w[16];

    int blk = blockIdx.x;
    int tid = threadIdx.x;

    if (blk < 2 * ND_BLOCKS) {
        // ---- descriptor normalize + transpose (fp32 -> int8*127) ----
        int which = blk >= ND_BLOCKS;
        int blk2 = blk - which * ND_BLOCKS;
        const float* src = which ? wdesc : desc;
        signed char* dst = which ? wdnorm : dnorm;
        int b = blk2 / (NN / 32);
        int jt = blk2 % (NN / 32);
        int base = jt * 32;
        const float* s = src + (size_t)b * DD * NN;
        #pragma unroll
        for (int q = 0; q < 4; q++) {
            int idx = tid + q * 512;       // < DD*8 = 2048 float4s
            int d = idx >> 3, j4 = idx & 7;
            float4 v4 = *(const float4*)(s + d * NN + base + j4 * 4);
            tile[d][j4 * 4 + 0] = v4.x;
            tile[d][j4 * 4 + 1] = v4.y;
            tile[d][j4 * 4 + 2] = v4.z;
            tile[d][j4 * 4 + 3] = v4.w;
        }
        __syncthreads();
        {
            int j = tid & 31, g = tid >> 5;
            float acc = 0;
            for (int d = g; d < DD; d += 16) { float v = tile[d][j]; acc += v * v; }
            part[g][j] = acc;
        }
        __syncthreads();
        if (tid < 32) {
            float s2 = 0;
            #pragma unroll
            for (int g2 = 0; g2 < 16; g2++) s2 += part[g2][tid];
            inv[tid] = 127.0f / fmaxf(sqrtf(s2), 1e-12f);
        }
        __syncthreads();
        signed char* o = dst + (size_t)b * NN * DD;
        for (int idx = tid; idx < 32 * DD; idx += 512) {
            int jj = idx >> 8, d = idx & 255;
            int q = __float2int_rn(tile[d][jj] * inv[jj]);
            q = max(-127, min(127, q));
            o[(size_t)(base + jj) * DD + d] = (signed char)q;
        }
    } else if (blk < 2 * ND_BLOCKS + DET_BLOCKS) {
        // ---- detector losses + normalization sum ----
        int i = (blk - 2 * ND_BLOCKS) * 512 + tid;   // exactly TOTAL_PIX/4 threads
        float vals[7];
        float4 p4 = ((const float4*)prob)[i], h4 = ((const float4*)ht)[i], v4 = ((const float4*)vm)[i];
        float4 wp4 = ((const float4*)wprob)[i], wh4 = ((const float4*)wht)[i], wv4 = ((const float4*)wvm)[i];
        #pragma unroll
        for (int q = 0; q < 7; q++) vals[q] = 0.f;
        #pragma unroll
        for (int q = 0; q < 4; q++) {
            float p = ((const float*)&p4)[q], h = ((const float*)&h4)[q], v = ((const float*)&v4)[q];
            float pi = (h == 1.0f) ? 1.f : 0.f;
            float ni = (h < 1.0f) ? 1.f : 0.f;
            float nw = (1.f - h) * (1.f - h); nw *= nw;
            if (pi * v != 0.f)            // measure-zero branch: pos term
                vals[0] += __logf(p + 1e-7f) * (1.f - p) * (1.f - p) * v;
            vals[1] += __logf(1.f - p + 1e-7f) * p * p * nw * ni * v;
            vals[2] += pi;
            float wp = ((const float*)&wp4)[q], wh = ((const float*)&wh4)[q], wv = ((const float*)&wv4)[q];
            float wpi = (wh == 1.0f) ? 1.f : 0.f;
            float wni = (wh < 1.0f) ? 1.f : 0.f;
            float wnw = (1.f - wh) * (1.f - wh); wnw *= wnw;
            if (wpi * wv != 0.f)
                vals[3] += __logf(wp + 1e-7f) * (1.f - wp) * (1.f - wp) * wv;
            vals[4] += __logf(1.f - wp + 1e-7f) * wp * wp * wnw * wni * wv;
            vals[5] += wpi;
            vals[6] += wv;
        }
        int lane = tid & 31, warp = tid >> 5;
        for (int q = 0; q < 7; q++) {
            float v = warpsum(vals[q]);
            if (lane == 0) w[warp] = v;
            __syncthreads();
            if (tid == 0) {
                float s = 0;
                #pragma unroll
                for (int u = 0; u < 16; u++) s += w[u];
                atomicAdd(&g_acc[q], (double)s);
            }
            __syncthreads();
        }
    } else {
        // ---- warped coords + downsampled masks ----
        int idx = (blk - 2 * ND_BLOCKS - DET_BLOCKS) * 512 + tid;
        if (idx < BB * NN) {
            int b = idx / NN, ij = idx % NN;
            int i = ij / WC, j = ij % WC;
            float y = (float)(i * 8 + 4), x = (float)(j * 8 + 4);
            const float* Hb = Hm + b * 9;
            float w0 = Hb[0] * x + Hb[1] * y + Hb[2];
            float w1 = Hb[3] * x + Hb[4] * y + Hb[5];
            float w2 = Hb[6] * x + Hb[7] * y + Hb[8];
            float vmc  = (bilinear_ds(vm  + (size_t)b * HH * WW, i, j) > 0.5f) ? 1.f : 0.f;
            float wvmc = (bilinear_ds(wvm + (size_t)b * HH * WW, i, j) > 0.5f) ? 1.f : 0.f;
            g_rowgeo[idx] = make_float4(w1 / w2, w0 / w2, vmc, 0.f);
            g_colgeo[idx] = make_float4(y, x, wvmc, 0.f);
        }
    }
}

// ---------------- main: int8 IMMA GEMM, full-K smem, split-load overlap ----------------
#define TM 96
#define TN 128
#define ASTRB 272                     // bytes/row: 256B data + 16B pad (17x16B, conflict-free)
#define A_BYTES (TM * ASTRB)          // 26112
#define B_BYTES (TN * ASTRB)          // 34816
#define ROW_OFF (A_BYTES + B_BYTES)   // 60928
#define COL_OFF (ROW_OFF + TM * 16)
#define WRED_OFF (COL_OFF + TN * 16)
#define SMEM_TOTAL (WRED_OFF + 48)
#define INV127SQ (1.0f / 16129.0f)

__device__ __forceinline__ float lossterm(float dotv, float4 r, float4 c) {
    float dot = fmaxf(dotv, 0.f);
    float pd = fmaxf(1.0f - dot, 0.f);
    float nd = fmaxf(dot - 0.2f, 0.f);
    float dy = c.x - r.x, dx = c.y - r.y;
    float d2 = dy * dy + dx * dx;
    float w = r.z * c.z;
    return (d2 <= 56.25f) ? 250.f * pd * w : nd * w;   // (CELL-0.5)^2 = 56.25
}

__global__ __launch_bounds__(384, 2) void gemm_loss_kernel() {
    extern __shared__ __align__(16) char dsm[];
    float4* s_row = (float4*)(dsm + ROW_OFF);
    float4* s_col = (float4*)(dsm + COL_OFF);
    float*  wred  = (float*)(dsm + WRED_OFF);

    int b = blockIdx.z;
    int i0 = blockIdx.y * TM;    // always full: 50*96 = 4800
    int j0 = blockIdx.x * TN;
    int tid = threadIdx.x;
    int wid = tid >> 5, lane = tid & 31;

    const char* A  = (const char*)g_dnorm  + (size_t)b * NN * DD;
    const char* Bm = (const char*)g_wdnorm + (size_t)b * NN * DD;
    uint32_t smem0 = smem_u32(dsm);

    // ---- split tile load: two K-halves (128B each), separate commit groups ----
    // per half: A = 96 rows x 8 segs = 768; B = 128 x 8 = 1024
    #pragma unroll
    for (int hh = 0; hh < 2; hh++) {
        int hb = hh * 128;
        #pragma unroll
        for (int q = 0; q < 2; q++) {
            int seg = tid + q * 384;           // < 768
            int row = seg >> 3, col = (seg & 7) * 16 + hb;
            cp_async16(smem0 + row * ASTRB + col, A + (size_t)(i0 + row) * DD + col, 16u);
        }
        #pragma unroll
        for (int q = 0; q < 3; q++) {
            int seg = tid + q * 384;
            if (seg < 1024) {
                int row = seg >> 3, col = (seg & 7) * 16 + hb;
                uint32_t ok = (j0 + row < NN) ? 16u : 0u;
                cp_async16(smem0 + A_BYTES + row * ASTRB + col,
                           Bm + (size_t)(j0 + row) * DD + col, ok);
            }
        }
        CP_COMMIT();
    }

    // geometry while the bulk copies fly
    if (tid < TM) {
        s_row[tid] = g_rowgeo[b * NN + i0 + tid];
    } else if (tid >= 128 && tid < 128 + TN) {
        int t = tid - 128;
        int c = j0 + t;
        s_col[t] = (c < NN) ? g_colgeo[b * NN + c] : make_float4(0.f, 0.f, 0.f, 0.f);
    }

    // 12 warps: 3(m) x 4(n) grid of 32x32 warp tiles
    int m_base = (wid >> 2) * 32;     // 0,32,64
    int n_base = (wid & 3) * 32;      // 0,32,64,96
    int g = lane >> 3, lr = lane & 7;

    int acc[2][4][4];
    #pragma unroll
    for (int i = 0; i < 2; i++)
        #pragma unroll
        for (int j = 0; j < 4; j++)
            #pragma unroll
            for (int q = 0; q < 4; q++) acc[i][j][q] = 0;

    uint32_t abase = smem0 + (uint32_t)((m_base + (g & 1) * 8 + lr) * ASTRB + (g >> 1) * 16);
    uint32_t bbase = smem0 + (uint32_t)A_BYTES
                   + (uint32_t)((n_base + (g >> 1) * 8 + lr) * ASTRB + (g & 1) * 16);

    #pragma unroll
    for (int half = 0; half < 2; half++) {
        if (half == 0) { CP_WAIT(1); } else { CP_WAIT(0); }
        __syncthreads();   // this K-half resident for all threads
        #pragma unroll
        for (int ki = 0; ki < 4; ki++) {         // K-step = 32 bytes
            int ks = half * 4 + ki;
            uint32_t af[2][4], bf[2][4];
            #pragma unroll
            for (int mt = 0; mt < 2; mt++) {
                uint32_t addr = abase + (uint32_t)(mt * 16 * ASTRB + ks * 32);
                asm volatile("ldmatrix.sync.aligned.m8n8.x4.shared.b16 {%0,%1,%2,%3}, [%4];"
                             : "=r"(af[mt][0]), "=r"(af[mt][1]), "=r"(af[mt][2]), "=r"(af[mt][3])
                             : "r"(addr));
            }
            #pragma unroll
            for (int np = 0; np < 2; np++) {
                uint32_t addr = bbase + (uint32_t)(np * 16 * ASTRB + ks * 32);
                asm volatile("ldmatrix.sync.aligned.m8n8.x4.shared.b16 {%0,%1,%2,%3}, [%4];"
                             : "=r"(bf[np][0]), "=r"(bf[np][1]), "=r"(bf[np][2]), "=r"(bf[np][3])
                             : "r"(addr));
            }
            #pragma unroll
            for (int np = 0; np < 2; np++)
                #pragma unroll
                for (int h = 0; h < 2; h++) {
                    int nt = np * 2 + h;
                    #pragma unroll
                    for (int mt = 0; mt < 2; mt++) {
                        asm volatile(
                            "mma.sync.aligned.m16n8k32.row.col.s32.s8.s8.s32 "
                            "{%0,%1,%2,%3}, {%4,%5,%6,%7}, {%8,%9}, {%0,%1,%2,%3};"
                            : "+r"(acc[mt][nt][0]), "+r"(acc[mt][nt][1]),
                              "+r"(acc[mt][nt][2]), "+r"(acc[mt][nt][3])
                            : "r"(af[mt][0]), "r"(af[mt][1]), "r"(af[mt][2]), "r"(af[mt][3]),
                              "r"(bf[np][h * 2]), "r"(bf[np][h * 2 + 1]));
                    }
                }
        }
    }

    // fused epilogue: c0=(qr,qc), c1=(qr,qc+1), c2=(qr+8,qc), c3=(qr+8,qc+1)
    int qr = lane >> 2, qc = (lane & 3) * 2;
    float lsum = 0.f;
    #pragma unroll
    for (int mt = 0; mt < 2; mt++) {
        float4 r0 = s_row[m_base + mt * 16 + qr];
        float4 r1 = s_row[m_base + mt * 16 + qr + 8];
        #pragma unroll
        for (int nt = 0; nt < 4; nt++) {
            float4 c0 = s_col[n_base + nt * 8 + qc];
            float4 c1 = s_col[n_base + nt * 8 + qc + 1];
            lsum += lossterm((float)acc[mt][nt][0] * INV127SQ, r0, c0);
            lsum += lossterm((float)acc[mt][nt][1] * INV127SQ, r0, c1);
            lsum += lossterm((float)acc[mt][nt][2] * INV127SQ, r1, c0);
            lsum += lossterm((float)acc[mt][nt][3] * INV127SQ, r1, c1);
        }
    }

    float v = warpsum(lsum);
    if (lane == 0) wred[wid] = v;
    __syncthreads();
    if (tid == 0) {
        float s = 0;
        #pragma unroll
        for (int u = 0; u < 12; u++) s += wred[u];
        atomicAdd(&g_acc[7], (double)s);
    }
}

// ---------------- finalize (also re-zeros accumulators for next replay) ----------------
__global__ void finalize_kernel(float* __restrict__ out) {
    double np1 = g_acc[2];
    double pl  = (np1 == 0.0) ? -g_acc[1] : -(g_acc[0] + g_acc[1]) / fmax(np1, 1.0);
    double np2 = g_acc[5];
    double wpl = (np2 == 0.0) ? -g_acc[4] : -(g_acc[3] + g_acc[4]) / fmax(np2, 1.0);
    double dl  = g_acc[7] / g_acc[6];
    out[0] = (float)(pl + wpl + 1e-4 * dl);
    out[1] = (float)pl;
    out[2] = (float)wpl;
    out[3] = (float)dl;
    #pragma unroll
    for (int q = 0; q < 8; q++) g_acc[q] = 0.0;
}

// ---------------- launch ----------------
extern "C" void kernel_launch(void* const* d_in, const int* in_sizes, int n_in,
                              void* d_out, int out_size) {
    const float* prob  = (const float*)d_in[0];
    const float* ht    = (const float*)d_in[1];
    const float* vm    = (const float*)d_in[2];
    const float* wprob = (const float*)d_in[3];
    const float* wht   = (const float*)d_in[4];
    const float* wvm   = (const float*)d_in[5];
    const float* desc  = (const float*)d_in[6];
    const float* wdesc = (const float*)d_in[7];
    const float* Hm    = (const float*)d_in[8];
    float* out = (float*)d_out;

    cudaFuncSetAttribute(gemm_loss_kernel,
                         cudaFuncAttributeMaxDynamicSharedMemorySize, SMEM_TOTAL);

    signed char* dnorm;  cudaGetSymbolAddress((void**)&dnorm,  g_dnorm);
    signed char* wdnorm; cudaGetSymbolAddress((void**)&wdnorm, g_wdnorm);

    prep_kernel<<<PREP_BLOCKS, 512>>>(prob, ht, vm, wprob, wht, wvm,
                                      desc, wdesc, Hm, dnorm, wdnorm);

    dim3 grid((NN + TN - 1) / TN, NN / TM, BB);
    gemm_loss_kernel<<<grid, 384, SMEM_TOTAL>>>();

    finalize_kernel<<<1, 1>>>(out);
}

// round 16
// speedup vs baseline: 1.5608x; 1.0263x over previous
#include <cuda_runtime.h>
#include <math.h>
#include <stdint.h>

#define BB 2
#define HH 480
#define WW 640
#define DD 256
#define HC 60
#define WC 80
#define NN 4800          // HC*WC
#define TOTAL_PIX (BB*HH*WW)

// ---------------- device scratch ----------------
// acc: 0 pos1, 1 neg1, 2 npos1, 3 pos2, 4 neg2, 5 npos2, 6 normalization, 7 desc_sum
__device__ double g_acc[8];   // static zero-init; finalize re-zeros after each use
__device__ __align__(16) signed char g_dnorm[BB*NN*DD];   // (b, ij, d) int8 normalized*127
__device__ __align__(16) signed char g_wdnorm[BB*NN*DD];
__device__ float4 g_rowgeo[BB*NN];   // {wy, wx, vm_c, 0}
__device__ float4 g_colgeo[BB*NN];   // {cy, cx, wvm_c, 0}

// ---------------- helpers ----------------
__device__ __forceinline__ float warpsum(float v) {
    #pragma unroll
    for (int o = 16; o; o >>= 1) v += __shfl_down_sync(0xffffffffu, v, o);
    return v;
}

__device__ __forceinline__ uint32_t smem_u32(const void* p) {
    uint32_t a;
    asm("{ .reg .u64 t; cvta.to.shared.u64 t, %1; cvt.u32.u64 %0, t; }" : "=r"(a) : "l"(p));
    return a;
}

__device__ __forceinline__ void cp_async16(uint32_t dst, const void* src, uint32_t bytes) {
    asm volatile("cp.async.cg.shared.global [%0], [%1], 16, %2;"
                 :: "r"(dst), "l"(src), "r"(bytes) : "memory");
}
#define CP_COMMIT() asm volatile("cp.async.commit_group;" ::: "memory")
#define CP_WAIT(n)  asm volatile("cp.async.wait_group %0;" :: "n"(n) : "memory")

// ---------------- fused prep: detector + normdesc + coords ----------------
__device__ __forceinline__ float bilinear_ds(const float* __restrict__ img, int i, int j) {
    float sr = (i + 0.5f) * ((float)HH / HC) - 0.5f;
    sr = fminf(fmaxf(sr, 0.f), (float)(HH - 1));
    int r0 = (int)floorf(sr); int r1 = min(r0 + 1, HH - 1); float wr = sr - (float)r0;
    float sc = (j + 0.5f) * ((float)WW / WC) - 0.5f;
    sc = fminf(fmaxf(sc, 0.f), (float)(WW - 1));
    int c0 = (int)floorf(sc); int c1 = min(c0 + 1, WW - 1); float wc = sc - (float)c0;
    float a = img[r0 * WW + c0] * (1.f - wr) + img[r1 * WW + c0] * wr;
    float b = img[r0 * WW + c1] * (1.f - wr) + img[r1 * WW + c1] * wr;
    return a * (1.f - wc) + b * wc;
}

#define ND_BLOCKS (BB * (NN / 32))        // 300 per tensor, 600 total
#define DET_BLOCKS (TOTAL_PIX / 4 / 512)  // 300
#define CRD_BLOCKS ((BB * NN + 511) / 512) // 19
#define PREP_BLOCKS (2 * ND_BLOCKS + DET_BLOCKS + CRD_BLOCKS)

__global__ __launch_bounds__(512) void prep_kernel(
    const float* __restrict__ prob, const float* __restrict__ ht,
    const float* __restrict__ vm, const float* __restrict__ wprob,
    const float* __restrict__ wht, const float* __restrict__ wvm,
    const float* __restrict__ desc, const float* __restrict__ wdesc,
    const float* __restrict__ Hm,
    signed char* __restrict__ dnorm, signed char* __restrict__ wdnorm)
{
    __shared__ float tile[DD][33];
    __shared__ float part[16][32];
    __shared__ float inv[32];
    __shared__ float w[16];

    int blk = blockIdx.x;
    int tid = threadIdx.x;

    if (blk < 2 * ND_BLOCKS) {
        // ---- descriptor normalize + transpose (fp32 -> int8*127) ----
        int which = blk >= ND_BLOCKS;
        int blk2 = blk - which * ND_BLOCKS;
        const float* src = which ? wdesc : desc;
        signed char* dst = which ? wdnorm : dnorm;
        int b = blk2 / (NN / 32);
        int jt = blk2 % (NN / 32);
        int base = jt * 32;
        const float* s = src + (size_t)b * DD * NN;
        #pragma unroll
        for (int q = 0; q < 4; q++) {
            int idx = tid + q * 512;       // < DD*8 = 2048 float4s
            int d = idx >> 3, j4 = idx & 7;
            float4 v4 = *(const float4*)(s + d * NN + base + j4 * 4);
            tile[d][j4 * 4 + 0] = v4.x;
            tile[d][j4 * 4 + 1] = v4.y;
            tile[d][j4 * 4 + 2] = v4.z;
            tile[d][j4 * 4 + 3] = v4.w;
        }
        __syncthreads();
        {
            int j = tid & 31, g = tid >> 5;
            float acc = 0;
            for (int d = g; d < DD; d += 16) { float v = tile[d][j]; acc += v * v; }
            part[g][j] = acc;
        }
        __syncthreads();
        if (tid < 32) {
            float s2 = 0;
            #pragma unroll
            for (int g2 = 0; g2 < 16; g2++) s2 += part[g2][tid];
            inv[tid] = 127.0f / fmaxf(sqrtf(s2), 1e-12f);
        }
        __syncthreads();
        signed char* o = dst + (size_t)b * NN * DD;
        for (int idx = tid; idx < 32 * DD; idx += 512) {
            int jj = idx >> 8, d = idx & 255;
            int q = __float2int_rn(tile[d][jj] * inv[jj]);
            q = max(-127, min(127, q));
            o[(size_t)(base + jj) * DD + d] = (signed char)q;
        }
    } else if (blk < 2 * ND_BLOCKS + DET_BLOCKS) {
        // ---- detector losses + normalization sum ----
        int i = (blk - 2 * ND_BLOCKS) * 512 + tid;   // exactly TOTAL_PIX/4 threads
        float vals[7];
        float4 p4 = ((const float4*)prob)[i], h4 = ((const float4*)ht)[i], v4 = ((const float4*)vm)[i];
        float4 wp4 = ((const float4*)wprob)[i], wh4 = ((const float4*)wht)[i], wv4 = ((const float4*)wvm)[i];
        #pragma unroll
        for (int q = 0; q < 7; q++) vals[q] = 0.f;
        #pragma unroll
        for (int q = 0; q < 4; q++) {
            float p = ((const float*)&p4)[q], h = ((const float*)&h4)[q], v = ((const float*)&v4)[q];
            float pi = (h == 1.0f) ? 1.f : 0.f;
            float ni = (h < 1.0f) ? 1.f : 0.f;
            float nw = (1.f - h) * (1.f - h); nw *= nw;
            if (pi * v != 0.f)            // measure-zero branch: pos term
                vals[0] += __logf(p + 1e-7f) * (1.f - p) * (1.f - p) * v;
            vals[1] += __logf(1.f - p + 1e-7f) * p * p * nw * ni * v;
            vals[2] += pi;
            float wp = ((const float*)&wp4)[q], wh = ((const float*)&wh4)[q], wv = ((const float*)&wv4)[q];
            float wpi = (wh == 1.0f) ? 1.f : 0.f;
            float wni = (wh < 1.0f) ? 1.f : 0.f;
            float wnw = (1.f - wh) * (1.f - wh); wnw *= wnw;
            if (wpi * wv != 0.f)
                vals[3] += __logf(wp + 1e-7f) * (1.f - wp) * (1.f - wp) * wv;
            vals[4] += __logf(1.f - wp + 1e-7f) * wp * wp * wnw * wni * wv;
            vals[5] += wpi;
            vals[6] += wv;
        }
        int lane = tid & 31, warp = tid >> 5;
        for (int q = 0; q < 7; q++) {
            float v = warpsum(vals[q]);
            if (lane == 0) w[warp] = v;
            __syncthreads();
            if (tid == 0) {
                float s = 0;
                #pragma unroll
                for (int u = 0; u < 16; u++) s += w[u];
                atomicAdd(&g_acc[q], (double)s);
            }
            __syncthreads();
        }
    } else {
        // ---- warped coords + downsampled masks ----
        int idx = (blk - 2 * ND_BLOCKS - DET_BLOCKS) * 512 + tid;
        if (idx < BB * NN) {
            int b = idx / NN, ij = idx % NN;
            int i = ij / WC, j = ij % WC;
            float y = (float)(i * 8 + 4), x = (float)(j * 8 + 4);
            const float* Hb = Hm + b * 9;
            float w0 = Hb[0] * x + Hb[1] * y + Hb[2];
            float w1 = Hb[3] * x + Hb[4] * y + Hb[5];
            float w2 = Hb[6] * x + Hb[7] * y + Hb[8];
            float vmc  = (bilinear_ds(vm  + (size_t)b * HH * WW, i, j) > 0.5f) ? 1.f : 0.f;
            float wvmc = (bilinear_ds(wvm + (size_t)b * HH * WW, i, j) > 0.5f) ? 1.f : 0.f;
            g_rowgeo[idx] = make_float4(w1 / w2, w0 / w2, vmc, 0.f);
            g_colgeo[idx] = make_float4(y, x, wvmc, 0.f);
        }
    }
}

// ---------------- main: int8 IMMA GEMM, one-shot full-K smem load ----------------
#define TM 96
#define TN 128
#define ASTRB 272                     // bytes/row: 256B data + 16B pad (17x16B, conflict-free)
#define A_BYTES (TM * ASTRB)          // 26112
#define B_BYTES (TN * ASTRB)          // 34816
#define ROW_OFF (A_BYTES + B_BYTES)   // 60928
#define COL_OFF (ROW_OFF + TM * 16)
#define WRED_OFF (COL_OFF + TN * 16)
#define SMEM_TOTAL (WRED_OFF + 48)
#define INV127SQ (1.0f / 16129.0f)

__device__ __forceinline__ float lossterm(float dotv, float4 r, float4 c) {
    float dot = fmaxf(dotv, 0.f);
    float pd = fmaxf(1.0f - dot, 0.f);
    float nd = fmaxf(dot - 0.2f, 0.f);
    float dy = c.x - r.x, dx = c.y - r.y;
    float d2 = dy * dy + dx * dx;
    float w = r.z * c.z;
    return (d2 <= 56.25f) ? 250.f * pd * w : nd * w;   // (CELL-0.5)^2 = 56.25
}

__global__ __launch_bounds__(384, 2) void gemm_loss_kernel() {
    extern __shared__ __align__(16) char dsm[];
    float4* s_row = (float4*)(dsm + ROW_OFF);
    float4* s_col = (float4*)(dsm + COL_OFF);
    float*  wred  = (float*)(dsm + WRED_OFF);

    int b = blockIdx.z;
    int i0 = blockIdx.y * TM;    // always full: 50*96 = 4800
    int j0 = blockIdx.x * TN;
    int tid = threadIdx.x;
    int wid = tid >> 5, lane = tid & 31;

    const char* A  = (const char*)g_dnorm  + (size_t)b * NN * DD;
    const char* Bm = (const char*)g_wdnorm + (size_t)b * NN * DD;
    uint32_t smem0 = smem_u32(dsm);

    // ---- one-shot tile load: A 96x256B (1536 segs), B 128x256B (2048 segs) ----
    #pragma unroll
    for (int q = 0; q < 4; q++) {
        int seg = tid + q * 384;           // < 1536 always
        int row = seg >> 4, col = (seg & 15) * 16;
        cp_async16(smem0 + row * ASTRB + col, A + (size_t)(i0 + row) * DD + col, 16u);
    }
    #pragma unroll
    for (int q = 0; q < 6; q++) {
        int seg = tid + q * 384;
        if (seg < 2048) {
            int row = seg >> 4, col = (seg & 15) * 16;
            uint32_t ok = (j0 + row < NN) ? 16u : 0u;
            cp_async16(smem0 + A_BYTES + row * ASTRB + col,
                       Bm + (size_t)(j0 + row) * DD + col, ok);
        }
    }
    CP_COMMIT();

    // geometry while the bulk copy flies
    if (tid < TM) {
        s_row[tid] = g_rowgeo[b * NN + i0 + tid];
    } else if (tid >= 128 && tid < 128 + TN) {
        int t = tid - 128;
        int c = j0 + t;
        s_col[t] = (c < NN) ? g_colgeo[b * NN + c] : make_float4(0.f, 0.f, 0.f, 0.f);
    }

    // 12 warps: 3(m) x 4(n) grid of 32x32 warp tiles
    int m_base = (wid >> 2) * 32;     // 0,32,64
    int n_base = (wid & 3) * 32;      // 0,32,64,96
    int g = lane >> 3, lr = lane & 7;

    int acc[2][4][4];
    #pragma unroll
    for (int i = 0; i < 2; i++)
        #pragma unroll
        for (int j = 0; j < 4; j++)
            #pragma unroll
            for (int q = 0; q < 4; q++) acc[i][j][q] = 0;

    uint32_t abase = smem0 + (uint32_t)((m_base + (g & 1) * 8 + lr) * ASTRB + (g >> 1) * 16);
    uint32_t bbase = smem0 + (uint32_t)A_BYTES
                   + (uint32_t)((n_base + (g >> 1) * 8 + lr) * ASTRB + (g & 1) * 16);

    CP_WAIT(0);
    __syncthreads();   // whole tile resident; no further barriers until epilogue

    #pragma unroll
    for (int ks = 0; ks < 8; ks++) {         // K-step = 32 bytes
        uint32_t af[2][4], bf[2][4];
        #pragma unroll
        for (int mt = 0; mt < 2; mt++) {
            uint32_t addr = abase + (uint32_t)(mt * 16 * ASTRB + ks * 32);
            asm volatile("ldmatrix.sync.aligned.m8n8.x4.shared.b16 {%0,%1,%2,%3}, [%4];"
                         : "=r"(af[mt][0]), "=r"(af[mt][1]), "=r"(af[mt][2]), "=r"(af[mt][3])
                         : "r"(addr));
        }
        #pragma unroll
        for (int np = 0; np < 2; np++) {
            uint32_t addr = bbase + (uint32_t)(np * 16 * ASTRB + ks * 32);
            asm volatile("ldmatrix.sync.aligned.m8n8.x4.shared.b16 {%0,%1,%2,%3}, [%4];"
                         : "=r"(bf[np][0]), "=r"(bf[np][1]), "=r"(bf[np][2]), "=r"(bf[np][3])
                         : "r"(addr));
        }
        #pragma unroll
        for (int np = 0; np < 2; np++)
            #pragma unroll
            for (int h = 0; h < 2; h++) {
                int nt = np * 2 + h;
                #pragma unroll
                for (int mt = 0; mt < 2; mt++) {
                    asm volatile(
                        "mma.sync.aligned.m16n8k32.row.col.s32.s8.s8.s32 "
                        "{%0,%1,%2,%3}, {%4,%5,%6,%7}, {%8,%9}, {%0,%1,%2,%3};"
                        : "+r"(acc[mt][nt][0]), "+r"(acc[mt][nt][1]),
                          "+r"(acc[mt][nt][2]), "+r"(acc[mt][nt][3])
                        : "r"(af[mt][0]), "r"(af[mt][1]), "r"(af[mt][2]), "r"(af[mt][3]),
                          "r"(bf[np][h * 2]), "r"(bf[np][h * 2 + 1]));
                }
            }
    }

    // fused epilogue: c0=(qr,qc), c1=(qr,qc+1), c2=(qr+8,qc), c3=(qr+8,qc+1)
    int qr = lane >> 2, qc = (lane & 3) * 2;
    float lsum = 0.f;
    #pragma unroll
    for (int mt = 0; mt < 2; mt++) {
        float4 r0 = s_row[m_base + mt * 16 + qr];
        float4 r1 = s_row[m_base + mt * 16 + qr + 8];
        #pragma unroll
        for (int nt = 0; nt < 4; nt++) {
            float4 c0 = s_col[n_base + nt * 8 + qc];
            float4 c1 = s_col[n_base + nt * 8 + qc + 1];
            lsum += lossterm((float)acc[mt][nt][0] * INV127SQ, r0, c0);
            lsum += lossterm((float)acc[mt][nt][1] * INV127SQ, r0, c1);
            lsum += lossterm((float)acc[mt][nt][2] * INV127SQ, r1, c0);
            lsum += lossterm((float)acc[mt][nt][3] * INV127SQ, r1, c1);
        }
    }

    float v = warpsum(lsum);
    if (lane == 0) wred[wid] = v;
    __syncthreads();
    if (tid == 0) {
        float s = 0;
        #pragma unroll
        for (int u = 0; u < 12; u++) s += wred[u];
        atomicAdd(&g_acc[7], (double)s);
    }
}

// ---------------- finalize (also re-zeros accumulators for next replay) ----------------
__global__ void finalize_kernel(float* __restrict__ out) {
    double np1 = g_acc[2];
    double pl  = (np1 == 0.0) ? -g_acc[1] : -(g_acc[0] + g_acc[1]) / fmax(np1, 1.0);
    double np2 = g_acc[5];
    double wpl = (np2 == 0.0) ? -g_acc[4] : -(g_acc[3] + g_acc[4]) / fmax(np2, 1.0);
    double dl  = g_acc[7] / g_acc[6];
    out[0] = (float)(pl + wpl + 1e-4 * dl);
    out[1] = (float)pl;
    out[2] = (float)wpl;
    out[3] = (float)dl;
    #pragma unroll
    for (int q = 0; q < 8; q++) g_acc[q] = 0.0;
}

// ---------------- launch ----------------
extern "C" void kernel_launch(void* const* d_in, const int* in_sizes, int n_in,
                              void* d_out, int out_size) {
    const float* prob  = (const float*)d_in[0];
    const float* ht    = (const float*)d_in[1];
    const float* vm    = (const float*)d_in[2];
    const float* wprob = (const float*)d_in[3];
    const float* wht   = (const float*)d_in[4];
    const float* wvm   = (const float*)d_in[5];
    const float* desc  = (const float*)d_in[6];
    const float* wdesc = (const float*)d_in[7];
    const float* Hm    = (const float*)d_in[8];
    float* out = (float*)d_out;

    cudaFuncSetAttribute(gemm_loss_kernel,
                         cudaFuncAttributeMaxDynamicSharedMemorySize, SMEM_TOTAL);

    signed char* dnorm;  cudaGetSymbolAddress((void**)&dnorm,  g_dnorm);
    signed char* wdnorm; cudaGetSymbolAddress((void**)&wdnorm, g_wdnorm);

    prep_kernel<<<PREP_BLOCKS, 512>>>(prob, ht, vm, wprob, wht, wvm,
                                      desc, wdesc, Hm, dnorm, wdnorm);

    dim3 grid((NN + TN - 1) / TN, NN / TM, BB);
    gemm_loss_kernel<<<grid, 384, SMEM_TOTAL>>>();

    finalize_kernel<<<1, 1>>>(out);
}